// round 13
// baseline (speedup 1.0000x reference)
#include <cuda_runtime.h>
#include <math.h>
#include <stdint.h>

#define BB 64
#define NN 32768
#define NQ 256
#define DD 256
#define HALF_N 16384   // points per CTA (cluster of 2)
#define TPB 512        // FPS threads per CTA (128-reg budget)
#define CH_PTS 2048    // points per chunk = TPB * 4
#define RED_WARP 15    // reduction warp (highest wid wins arbiter vs spinners)

// ---------------------------------------------------------------------------
// helpers
// ---------------------------------------------------------------------------
__device__ __forceinline__ uint32_t smem_u32(const void* p) {
    uint32_t a;
    asm("{ .reg .u64 t; cvta.to.shared.u64 t, %1; cvt.u32.u64 %0, t; }"
        : "=r"(a) : "l"(p));
    return a;
}

// store 5 data words into the peer CTA's mailbox slot (relaxed)
__device__ __forceinline__ void st_peer_entry(uint32_t laddr, uint32_t peer,
                                              uint32_t w0, uint32_t w1,
                                              uint32_t w2, uint32_t w3,
                                              uint32_t w4) {
    asm volatile(
        "{\n\t"
        ".reg .b32 r;\n\t"
        "mapa.shared::cluster.u32 r, %0, %1;\n\t"
        "st.shared::cluster.v4.b32 [r], {%2, %3, %4, %5};\n\t"
        "st.shared::cluster.b32 [r+16], %6;\n\t"
        "}"
        :: "r"(laddr), "r"(peer), "r"(w0), "r"(w1), "r"(w2), "r"(w3), "r"(w4)
        : "memory");
}

// release-store the seq word in the peer CTA (orders the prior data stores)
__device__ __forceinline__ void st_peer_seq_release(uint32_t laddr, uint32_t peer,
                                                    uint32_t v) {
    asm volatile(
        "{\n\t"
        ".reg .b32 r;\n\t"
        "mapa.shared::cluster.u32 r, %0, %1;\n\t"
        "st.release.cluster.shared::cluster.b32 [r], %2;\n\t"
        "}"
        :: "r"(laddr), "r"(peer), "r"(v) : "memory");
}

// release-store the local seq word (cluster scope so peer-side loads pair too)
__device__ __forceinline__ void st_local_seq_release(uint32_t a, uint32_t v) {
    asm volatile("st.release.cluster.shared::cta.b32 [%0], %1;"
                 :: "r"(a), "r"(v) : "memory");
}

__device__ __forceinline__ uint32_t ld_acq_seq(uint32_t a) {
    uint32_t v;
    asm volatile("ld.acquire.cluster.shared::cta.b32 %0, [%1];"
                 : "=r"(v) : "r"(a) : "memory");
    return v;
}

#define CLUSTER_SYNC_()                                                  \
    do {                                                                 \
        asm volatile("barrier.cluster.arrive.aligned;" ::: "memory");    \
        asm volatile("barrier.cluster.wait.aligned;" ::: "memory");      \
    } while (0)

#define BAR_ARRIVE_1()  asm volatile("bar.arrive 1, 512;" ::: "memory")
#define BAR_SYNC_1()    asm volatile("bar.sync 1, 512;" ::: "memory")

// packed f32x2 fma (MLP; benched equal to scalar)
__device__ __forceinline__ void ffma2(unsigned long long& acc,
                                      unsigned long long a, unsigned long long b) {
    asm("fma.rn.f32x2 %0, %1, %2, %0;" : "+l"(acc) : "l"(a), "l"(b));
}
__device__ __forceinline__ unsigned long long pack2(float lo, float hi) {
    unsigned long long r;
    asm("mov.b64 %0, {%1, %2};" : "=l"(r) : "f"(lo), "f"(hi));
    return r;
}
__device__ __forceinline__ void unpack2(float& lo, float& hi, unsigned long long v) {
    asm("mov.b64 {%0, %1}, %2;" : "=f"(lo), "=f"(hi) : "l"(v));
}

// ---------------------------------------------------------------------------
// FPS: 64 clusters x 2 CTAs, 512 threads x 32 pts/thread (128-reg budget).
// Chunks 0-1: coords in registers, direct distance (R8-proven rounding).
// Chunks 2-7: coords from smem, shifted form D=min(-2p.c+|c|^2), true distance
//             D+pn for compares (R12-proven rounding), pn[24] in registers.
// REDUX argmax in warp 15; cross-CTA exchange via DSMEM mailbox + release-
// store seq word + acquire-spin (no mbarrier, no cluster.sync per step).
// ---------------------------------------------------------------------------
__global__ __launch_bounds__(TPB, 1) __cluster_dims__(2, 1, 1)
void fps_kernel(const float* __restrict__ xyz, float* __restrict__ out_xyz) {
    extern __shared__ float sm[];
    float* sxp = sm;
    float* syp = sm + HALF_N;
    float* szp = sm + 2 * HALF_N;

    __shared__ unsigned s_val[16];
    __shared__ unsigned s_idx[16];
    __shared__ __align__(16) float    mb[2][2][8];  // [buf][src_rank][val,idx,x,y,z]
    __shared__ __align__(16) unsigned sq[2][2];     // [buf][src_rank] seq words

    const int b    = blockIdx.x >> 1;
    const int rank = blockIdx.x & 1;
    const int t    = threadIdx.x;
    const int wrp  = t >> 5;

    if (t < 4) ((unsigned*)sq)[t] = 0u;

    const float* gx = xyz + ((size_t)b * NN + (size_t)rank * HALF_N) * 3;
    for (int i = t; i < HALF_N; i += TPB) {
        const float* p = gx + 3 * i;
        sxp[i] = p[0];
        syp[i] = p[1];
        szp[i] = p[2];
    }

    const float* p0 = xyz + (size_t)b * NN * 3;
    float cx = __ldg(&p0[0]);
    float cy = __ldg(&p0[1]);
    float cz = __ldg(&p0[2]);
    if (rank == 0 && t == 0) {
        float* o = out_xyz + (size_t)b * NQ * 3;
        o[0] = cx; o[1] = cy; o[2] = cz;
    }
    __syncthreads();
    CLUSTER_SYNC_();   // seq-word zero-init must be visible before peer stores

    // hoist chunks 0-1 coordinates into registers (loop-invariant)
    float4 hx[2], hy[2], hz[2];
#pragma unroll
    for (int c = 0; c < 2; c++) {
        const int base = c * CH_PTS + t * 4;
        hx[c] = *(const float4*)(sxp + base);
        hy[c] = *(const float4*)(syp + base);
        hz[c] = *(const float4*)(szp + base);
    }

    // |p|^2 for chunks 2-7 (one-time, 24 registers)
    float pn[24];
#pragma unroll
    for (int ch = 2; ch < 8; ch++) {
        const int base = ch * CH_PTS + t * 4;
        float4 px = *(const float4*)(sxp + base);
        float4 py = *(const float4*)(syp + base);
        float4 pz = *(const float4*)(szp + base);
        const int o = (ch - 2) * 4;
        pn[o + 0] = __fmaf_rn(px.x, px.x, __fmaf_rn(py.x, py.x, __fmul_rn(pz.x, pz.x)));
        pn[o + 1] = __fmaf_rn(px.y, px.y, __fmaf_rn(py.y, py.y, __fmul_rn(pz.y, pz.y)));
        pn[o + 2] = __fmaf_rn(px.z, px.z, __fmaf_rn(py.z, py.z, __fmul_rn(pz.z, pz.z)));
        pn[o + 3] = __fmaf_rn(px.w, px.w, __fmaf_rn(py.w, py.w, __fmul_rn(pz.w, pz.w)));
    }

    float D[32];
#pragma unroll
    for (int i = 0; i < 32; i++) D[i] = 1e10f;

    const uint32_t peer = 1 - rank;

    for (int k = 1; k < NQ; k++) {
        const int buf = k & 1;
        const float m2x = -2.0f * cx;
        const float m2y = -2.0f * cy;
        const float m2z = -2.0f * cz;
        const float cc  = __fmaf_rn(cx, cx, __fmaf_rn(cy, cy, __fmul_rn(cz, cz)));

        float best = 0.0f;    // distances are >= 0
        int bidx = 0;

        // chunks 0-1: direct contracted distance from registers
#define FPS_DIR(VX, VY, VZ, SLOT, IDX)                                         \
        do {                                                                   \
            float dx = (VX) - cx, dy = (VY) - cy, dz = (VZ) - cz;              \
            float dsq = __fmaf_rn(dx, dx, __fmaf_rn(dy, dy,                    \
                                  __fmul_rn(dz, dz)));                         \
            float dn = fminf(D[SLOT], dsq);                                    \
            D[SLOT] = dn;                                                      \
            if (dn > best) { best = dn; bidx = (IDX); }                        \
        } while (0)

#pragma unroll
        for (int c = 0; c < 2; c++) {
            const int base = c * CH_PTS + t * 4;
            FPS_DIR(hx[c].x, hy[c].x, hz[c].x, c * 4 + 0, base + 0);
            FPS_DIR(hx[c].y, hy[c].y, hz[c].y, c * 4 + 1, base + 1);
            FPS_DIR(hx[c].z, hy[c].z, hz[c].z, c * 4 + 2, base + 2);
            FPS_DIR(hx[c].w, hy[c].w, hz[c].w, c * 4 + 3, base + 3);
        }
#undef FPS_DIR

        // chunks 2-7: shifted form from smem
#define FPS_SH(VX, VY, VZ, SLOT, PO, IDX)                                      \
        do {                                                                   \
            float q = __fmaf_rn((VX), m2x, __fmaf_rn((VY), m2y,                \
                        __fmaf_rn((VZ), m2z, cc)));                            \
            float Dn = fminf(D[SLOT], q);                                      \
            D[SLOT] = Dn;                                                      \
            float dn = __fadd_rn(Dn, pn[PO]);                                  \
            if (dn > best) { best = dn; bidx = (IDX); }                        \
        } while (0)

#pragma unroll
        for (int ch = 2; ch < 8; ch++) {
            const int base = ch * CH_PTS + t * 4;
            const int o = (ch - 2) * 4;
            float4 px = *(const float4*)(sxp + base);
            float4 py = *(const float4*)(syp + base);
            float4 pz = *(const float4*)(szp + base);
            FPS_SH(px.x, py.x, pz.x, ch * 4 + 0, o + 0, base + 0);
            FPS_SH(px.y, py.y, pz.y, ch * 4 + 1, o + 1, base + 1);
            FPS_SH(px.z, py.z, pz.z, ch * 4 + 2, o + 2, base + 2);
            FPS_SH(px.w, py.w, pz.w, ch * 4 + 3, o + 3, base + 3);
        }
#undef FPS_SH

        unsigned gidx = (unsigned)((rank << 14) + bidx);

        // stage 1: warp argmax via REDUX (positive fp32 bits are u32-monotone);
        // exact first-index tie-break via min over index of max-ties
        unsigned bb = __float_as_uint(best);
        unsigned mv = __reduce_max_sync(0xffffffffu, bb);
        unsigned cand = (bb == mv) ? gidx : 0xffffffffu;
        unsigned mi = __reduce_min_sync(0xffffffffu, cand);
        if ((t & 31) == 0) { s_val[wrp] = mv; s_idx[wrp] = mi; }

        if (wrp != RED_WARP) {
            BAR_ARRIVE_1();            // hand results to warp 15, go spin
        } else {
            BAR_SYNC_1();              // wait for the other 15 warps
            const int l = t & 31;
            unsigned wv = (l < 16) ? s_val[l] : 0u;
            unsigned wi = (l < 16) ? s_idx[l] : 0xffffffffu;
            unsigned mv2 = __reduce_max_sync(0xffffffffu, wv);
            unsigned cand2 = (wv == mv2) ? wi : 0xffffffffu;
            unsigned mi2 = __reduce_min_sync(0xffffffffu, cand2);
            if (l == 0) {
                int loc = (int)(mi2 & (HALF_N - 1));
                float wx = sxp[loc], wy = syp[loc], wz = szp[loc];
                // local mailbox + release seq
                mb[buf][rank][0] = __uint_as_float(mv2);
                mb[buf][rank][1] = __uint_as_float(mi2);
                mb[buf][rank][2] = wx;
                mb[buf][rank][3] = wy;
                mb[buf][rank][4] = wz;
                st_local_seq_release(smem_u32(&sq[buf][rank]), (unsigned)k);
                // peer mailbox (DSMEM) + release seq
                st_peer_entry(smem_u32(&mb[buf][rank][0]), peer,
                              mv2, mi2,
                              __float_as_uint(wx), __float_as_uint(wy),
                              __float_as_uint(wz));
                st_peer_seq_release(smem_u32(&sq[buf][rank]), peer, (unsigned)k);
            }
        }

        // spin until both CTAs' results for step k have landed
        {
            const uint32_t a0 = smem_u32(&sq[buf][0]);
            const uint32_t a1 = smem_u32(&sq[buf][1]);
            while (ld_acq_seq(a0) != (unsigned)k || ld_acq_seq(a1) != (unsigned)k) { }
        }

        // cluster-wide winner: compare as (value bits desc, index asc)
        unsigned v0 = __float_as_uint(mb[buf][0][0]);
        unsigned v1 = __float_as_uint(mb[buf][1][0]);
        unsigned i0 = __float_as_uint(mb[buf][0][1]);
        unsigned i1 = __float_as_uint(mb[buf][1][1]);
        int w = (v1 > v0 || (v1 == v0 && i1 < i0)) ? 1 : 0;
        cx = mb[buf][w][2];
        cy = mb[buf][w][3];
        cz = mb[buf][w][4];

        if (rank == 0 && t == RED_WARP * 32) {
            float* o = out_xyz + ((size_t)b * NQ + k) * 3;
            o[0] = cx; o[1] = cy; o[2] = cz;
        }
    }
}

// ---------------------------------------------------------------------------
// Fused fourier pos-embed + 2-layer MLP (benched 128 us; unchanged).
// ---------------------------------------------------------------------------
#define MT 512
#define PPITCH 132
#define WPITCH 260

__global__ __launch_bounds__(MT, 1)
void mlp_kernel(const float* __restrict__ qxyz,
                const float* __restrict__ pc_min, const float* __restrict__ pc_max,
                const float* __restrict__ gB,
                const float* __restrict__ W1, const float* __restrict__ b1,
                const float* __restrict__ W2, const float* __restrict__ b2,
                float* __restrict__ out_emb) {
    extern __shared__ float sm[];
    float* Pm = sm;                          // [256][PPITCH]
    float* Wt = sm + 256 * PPITCH;           // [64][WPITCH]
    float* qn = Wt + 64 * WPITCH;            // [3][128]

    const int b  = blockIdx.x >> 1;
    const int n0 = (blockIdx.x & 1) * 128;
    const int t  = threadIdx.x;
    const int tn = t & 15;
    const int td = t >> 4;

    if (t < 128) {
        const float* p = qxyz + ((size_t)b * NQ + n0 + t) * 3;
#pragma unroll
        for (int a = 0; a < 3; a++) {
            float mn = pc_min[b * 3 + a];
            float mx = pc_max[b * 3 + a];
            qn[a * 128 + t] = (p[a] - mn) / (mx - mn);
        }
    }
    __syncthreads();

    const float TWO_PI = 6.28318530717958647692f;
#pragma unroll
    for (int r = 0; r < 32; r++) {
        int i = r * MT + t;
        int n = i & 127;
        int f = i >> 7;
        float pr = qn[n] * gB[f] + qn[128 + n] * gB[128 + f] + qn[256 + n] * gB[256 + f];
        pr *= TWO_PI;
        float s, c;
        __sincosf(pr, &s, &c);
        Pm[f * PPITCH + n]          = s;
        Pm[(f + 128) * PPITCH + n]  = c;
    }

    unsigned long long acc2[8][4];

    // ===== layer 1: H = relu(W1 @ P + b1) =====
#pragma unroll
    for (int i = 0; i < 8; i++)
#pragma unroll
        for (int j = 0; j < 4; j++) acc2[i][j] = 0ull;

    for (int ct = 0; ct < 4; ct++) {
        __syncthreads();
#pragma unroll
        for (int r = 0; r < 32; r++) {
            int i = r * MT + t;
            int c = i & 63;
            int d = i >> 6;
            Wt[c * WPITCH + d] = W1[(size_t)d * 256 + ct * 64 + c];
        }
        __syncthreads();
#pragma unroll 4
        for (int c = 0; c < 64; c++) {
            const float* pr = Pm + (ct * 64 + c) * PPITCH + 8 * tn;
            float4 p0 = *(const float4*)pr;
            float4 p1 = *(const float4*)(pr + 4);
            const float* wr = Wt + c * WPITCH + 8 * td;
            float4 w0 = *(const float4*)wr;
            float4 w1 = *(const float4*)(wr + 4);
            unsigned long long pv2[4] = {pack2(p0.x, p0.y), pack2(p0.z, p0.w),
                                         pack2(p1.x, p1.y), pack2(p1.z, p1.w)};
            float wv[8] = {w0.x, w0.y, w0.z, w0.w, w1.x, w1.y, w1.z, w1.w};
#pragma unroll
            for (int i = 0; i < 8; i++) {
                unsigned long long wv2 = pack2(wv[i], wv[i]);
#pragma unroll
                for (int j = 0; j < 4; j++)
                    ffma2(acc2[i][j], wv2, pv2[j]);
            }
        }
    }
    __syncthreads();
#pragma unroll
    for (int i = 0; i < 8; i++) {
        int d = 8 * td + i;
        float bb = b1[d];
        float v[8];
#pragma unroll
        for (int j = 0; j < 4; j++) unpack2(v[2 * j], v[2 * j + 1], acc2[i][j]);
        float* hr = Pm + d * PPITCH + 8 * tn;
        float4 o0 = make_float4(fmaxf(v[0] + bb, 0.f), fmaxf(v[1] + bb, 0.f),
                                fmaxf(v[2] + bb, 0.f), fmaxf(v[3] + bb, 0.f));
        float4 o1 = make_float4(fmaxf(v[4] + bb, 0.f), fmaxf(v[5] + bb, 0.f),
                                fmaxf(v[6] + bb, 0.f), fmaxf(v[7] + bb, 0.f));
        *(float4*)hr       = o0;
        *(float4*)(hr + 4) = o1;
    }

    // ===== layer 2: E = relu(W2 @ H + b2) =====
#pragma unroll
    for (int i = 0; i < 8; i++)
#pragma unroll
        for (int j = 0; j < 4; j++) acc2[i][j] = 0ull;

    for (int ct = 0; ct < 4; ct++) {
        __syncthreads();
#pragma unroll
        for (int r = 0; r < 32; r++) {
            int i = r * MT + t;
            int c = i & 63;
            int d = i >> 6;
            Wt[c * WPITCH + d] = W2[(size_t)d * 256 + ct * 64 + c];
        }
        __syncthreads();
#pragma unroll 4
        for (int c = 0; c < 64; c++) {
            const float* pr = Pm + (ct * 64 + c) * PPITCH + 8 * tn;
            float4 p0 = *(const float4*)pr;
            float4 p1 = *(const float4*)(pr + 4);
            const float* wr = Wt + c * WPITCH + 8 * td;
            float4 w0 = *(const float4*)wr;
            float4 w1 = *(const float4*)(wr + 4);
            unsigned long long pv2[4] = {pack2(p0.x, p0.y), pack2(p0.z, p0.w),
                                         pack2(p1.x, p1.y), pack2(p1.z, p1.w)};
            float wv[8] = {w0.x, w0.y, w0.z, w0.w, w1.x, w1.y, w1.z, w1.w};
#pragma unroll
            for (int i = 0; i < 8; i++) {
                unsigned long long wv2 = pack2(wv[i], wv[i]);
#pragma unroll
                for (int j = 0; j < 4; j++)
                    ffma2(acc2[i][j], wv2, pv2[j]);
            }
        }
    }

#pragma unroll
    for (int i = 0; i < 8; i++) {
        int d = 8 * td + i;
        float bb = b2[d];
        float v[8];
#pragma unroll
        for (int j = 0; j < 4; j++) unpack2(v[2 * j], v[2 * j + 1], acc2[i][j]);
        float* dst = out_emb + ((size_t)b * DD + d) * NQ + n0 + 8 * tn;
        float4 o0 = make_float4(fmaxf(v[0] + bb, 0.f), fmaxf(v[1] + bb, 0.f),
                                fmaxf(v[2] + bb, 0.f), fmaxf(v[3] + bb, 0.f));
        float4 o1 = make_float4(fmaxf(v[4] + bb, 0.f), fmaxf(v[5] + bb, 0.f),
                                fmaxf(v[6] + bb, 0.f), fmaxf(v[7] + bb, 0.f));
        *(float4*)dst       = o0;
        *(float4*)(dst + 4) = o1;
    }
}

// ---------------------------------------------------------------------------
// launch
// ---------------------------------------------------------------------------
extern "C" void kernel_launch(void* const* d_in, const int* in_sizes, int n_in,
                              void* d_out, int out_size) {
    const float* xyz   = (const float*)d_in[0];
    const float* pcmin = (const float*)d_in[1];
    const float* pcmax = (const float*)d_in[2];
    const float* gB    = (const float*)d_in[3];
    const float* W1    = (const float*)d_in[4];
    const float* b1    = (const float*)d_in[5];
    const float* W2    = (const float*)d_in[6];
    const float* b2    = (const float*)d_in[7];

    float* out     = (float*)d_out;
    float* out_xyz = out;                              // [B][NQ][3]
    float* out_emb = out + (size_t)BB * NQ * 3;        // [B][D][NQ]

    const int fps_smem = 3 * HALF_N * 4;               // 196608 B
    const int mlp_smem = (256 * PPITCH + 64 * WPITCH + 3 * 128) * 4;
    cudaFuncSetAttribute(fps_kernel, cudaFuncAttributeMaxDynamicSharedMemorySize, fps_smem);
    cudaFuncSetAttribute(mlp_kernel, cudaFuncAttributeMaxDynamicSharedMemorySize, mlp_smem);

    fps_kernel<<<BB * 2, TPB, fps_smem>>>(xyz, out_xyz);
    mlp_kernel<<<BB * 2, MT, mlp_smem>>>(out_xyz, pcmin, pcmax, gB,
                                         W1, b1, W2, b2, out_emb);
}

// round 16
// speedup vs baseline: 1.1507x; 1.1507x over previous
#include <cuda_runtime.h>
#include <math.h>
#include <stdint.h>

#define BB 64
#define NN 32768
#define NQ 256
#define DD 256
#define HALF_N 16384   // points per CTA (cluster of 2)
#define TPB 512        // FPS threads per CTA (128-reg budget)
#define CH_PTS 2048    // points per chunk = TPB * 4

// ---------------------------------------------------------------------------
// helpers
// ---------------------------------------------------------------------------
__device__ __forceinline__ uint32_t smem_u32(const void* p) {
    uint32_t a;
    asm("{ .reg .u64 t; cvta.to.shared.u64 t, %1; cvt.u32.u64 %0, t; }"
        : "=r"(a) : "l"(p));
    return a;
}

__device__ __forceinline__ void st_peer_entry(uint32_t laddr, uint32_t peer,
                                              uint32_t w0, uint32_t w1,
                                              uint32_t w2, uint32_t w3,
                                              uint32_t w4) {
    asm volatile(
        "{\n\t"
        ".reg .b32 r;\n\t"
        "mapa.shared::cluster.u32 r, %0, %1;\n\t"
        "st.shared::cluster.v4.b32 [r], {%2, %3, %4, %5};\n\t"
        "st.shared::cluster.b32 [r+16], %6;\n\t"
        "}"
        :: "r"(laddr), "r"(peer), "r"(w0), "r"(w1), "r"(w2), "r"(w3), "r"(w4)
        : "memory");
}

#define CLUSTER_SYNC_()                                                  \
    do {                                                                 \
        asm volatile("barrier.cluster.arrive.aligned;" ::: "memory");    \
        asm volatile("barrier.cluster.wait.aligned;" ::: "memory");      \
    } while (0)

__device__ __forceinline__ void mbar_init(uint32_t a, uint32_t count) {
    asm volatile("mbarrier.init.shared.b64 [%0], %1;" :: "r"(a), "r"(count) : "memory");
}
__device__ __forceinline__ void mbar_arrive_local(uint32_t a) {
    asm volatile("mbarrier.arrive.release.cta.shared::cta.b64 _, [%0];"
                 :: "r"(a) : "memory");
}
__device__ __forceinline__ void mbar_arrive_peer(uint32_t a, uint32_t peer) {
    asm volatile(
        "{\n\t"
        ".reg .b32 r;\n\t"
        "mapa.shared::cluster.u32 r, %0, %1;\n\t"
        "mbarrier.arrive.release.cluster.shared::cluster.b64 _, [r];\n\t"
        "}"
        :: "r"(a), "r"(peer) : "memory");
}
__device__ __forceinline__ void mbar_wait_parity(uint32_t a, uint32_t parity) {
    asm volatile(
        "{\n\t"
        ".reg .pred P;\n\t"
        "WL_%=:\n\t"
        "mbarrier.try_wait.parity.acquire.cluster.shared::cta.b64 P, [%0], %1, 0x989680;\n\t"
        "@P bra.uni WD_%=;\n\t"
        "bra.uni WL_%=;\n\t"
        "WD_%=:\n\t"
        "}"
        :: "r"(a), "r"(parity) : "memory");
}

#define BAR_ARRIVE_1()  asm volatile("bar.arrive 1, 512;" ::: "memory")
#define BAR_SYNC_1()    asm volatile("bar.sync 1, 512;" ::: "memory")

// packed f32x2 fma (MLP; benched equal to scalar)
__device__ __forceinline__ void ffma2(unsigned long long& acc,
                                      unsigned long long a, unsigned long long b) {
    asm("fma.rn.f32x2 %0, %1, %2, %0;" : "+l"(acc) : "l"(a), "l"(b));
}
__device__ __forceinline__ unsigned long long pack2(float lo, float hi) {
    unsigned long long r;
    asm("mov.b64 %0, {%1, %2};" : "=l"(r) : "f"(lo), "f"(hi));
    return r;
}
__device__ __forceinline__ void unpack2(float& lo, float& hi, unsigned long long v) {
    asm("mov.b64 {%0, %1}, %2;" : "=f"(lo), "=f"(hi) : "l"(v));
}

// cp.async 4-byte G->S copy
__device__ __forceinline__ void cp_async_f32(uint32_t dst, const float* src) {
    asm volatile("cp.async.ca.shared.global [%0], [%1], 4;"
                 :: "r"(dst), "l"(src) : "memory");
}
#define CP_COMMIT() asm volatile("cp.async.commit_group;" ::: "memory")
#define CP_WAIT0()  asm volatile("cp.async.wait_group 0;" ::: "memory")

// ---------------------------------------------------------------------------
// FPS (R12 kernel, verbatim): 64 clusters x 2 CTAs, 512 threads x 32 pts.
// ---------------------------------------------------------------------------
__global__ __launch_bounds__(TPB, 1) __cluster_dims__(2, 1, 1)
void fps_kernel(const float* __restrict__ xyz, float* __restrict__ out_xyz) {
    extern __shared__ float sm[];
    float* sxp = sm;
    float* syp = sm + HALF_N;
    float* szp = sm + 2 * HALF_N;

    __shared__ unsigned s_val[16];
    __shared__ unsigned s_idx[16];
    __shared__ __align__(16) float mb[2][2][8];   // [buf][rank][val,idx,x,y,z]
    __shared__ __align__(8) unsigned long long xbar;

    const int b    = blockIdx.x >> 1;
    const int rank = blockIdx.x & 1;
    const int t    = threadIdx.x;
    const int wrp  = t >> 5;
    const uint32_t xbar_a = smem_u32(&xbar);

    if (t == 0) mbar_init(xbar_a, 2);

    const float* gx = xyz + ((size_t)b * NN + (size_t)rank * HALF_N) * 3;
    for (int i = t; i < HALF_N; i += TPB) {
        const float* p = gx + 3 * i;
        sxp[i] = p[0];
        syp[i] = p[1];
        szp[i] = p[2];
    }

    const float* p0 = xyz + (size_t)b * NN * 3;
    float cx = __ldg(&p0[0]);
    float cy = __ldg(&p0[1]);
    float cz = __ldg(&p0[2]);
    if (rank == 0 && t == 0) {
        float* o = out_xyz + (size_t)b * NQ * 3;
        o[0] = cx; o[1] = cy; o[2] = cz;
    }
    __syncthreads();
    CLUSTER_SYNC_();   // peer's mbarrier init must be visible before remote arrives

    // hoist chunks 0-1 coordinates into registers (loop-invariant)
    float4 hx[2], hy[2], hz[2];
#pragma unroll
    for (int c = 0; c < 2; c++) {
        const int base = c * CH_PTS + t * 4;
        hx[c] = *(const float4*)(sxp + base);
        hy[c] = *(const float4*)(syp + base);
        hz[c] = *(const float4*)(szp + base);
    }

    // |p|^2 for chunks 2-7 (one-time, 24 registers)
    float pn[24];
#pragma unroll
    for (int ch = 2; ch < 8; ch++) {
        const int base = ch * CH_PTS + t * 4;
        float4 px = *(const float4*)(sxp + base);
        float4 py = *(const float4*)(syp + base);
        float4 pz = *(const float4*)(szp + base);
        const int o = (ch - 2) * 4;
        pn[o + 0] = __fmaf_rn(px.x, px.x, __fmaf_rn(py.x, py.x, __fmul_rn(pz.x, pz.x)));
        pn[o + 1] = __fmaf_rn(px.y, px.y, __fmaf_rn(py.y, py.y, __fmul_rn(pz.y, pz.y)));
        pn[o + 2] = __fmaf_rn(px.z, px.z, __fmaf_rn(py.z, py.z, __fmul_rn(pz.z, pz.z)));
        pn[o + 3] = __fmaf_rn(px.w, px.w, __fmaf_rn(py.w, py.w, __fmul_rn(pz.w, pz.w)));
    }

    float D[32];
#pragma unroll
    for (int i = 0; i < 32; i++) D[i] = 1e10f;

    const uint32_t peer = 1 - rank;
    int buf = 1;

    for (int k = 1; k < NQ; k++) {
        const float m2x = -2.0f * cx;
        const float m2y = -2.0f * cy;
        const float m2z = -2.0f * cz;
        const float cc  = __fmaf_rn(cx, cx, __fmaf_rn(cy, cy, __fmul_rn(cz, cz)));

        float best = 0.0f;    // distances are >= 0
        int bidx = 0;

#define FPS_DIR(VX, VY, VZ, SLOT, IDX)                                         \
        do {                                                                   \
            float dx = (VX) - cx, dy = (VY) - cy, dz = (VZ) - cz;              \
            float dsq = __fmaf_rn(dx, dx, __fmaf_rn(dy, dy,                    \
                                  __fmul_rn(dz, dz)));                         \
            float dn = fminf(D[SLOT], dsq);                                    \
            D[SLOT] = dn;                                                      \
            if (dn > best) { best = dn; bidx = (IDX); }                        \
        } while (0)

#pragma unroll
        for (int c = 0; c < 2; c++) {
            const int base = c * CH_PTS + t * 4;
            FPS_DIR(hx[c].x, hy[c].x, hz[c].x, c * 4 + 0, base + 0);
            FPS_DIR(hx[c].y, hy[c].y, hz[c].y, c * 4 + 1, base + 1);
            FPS_DIR(hx[c].z, hy[c].z, hz[c].z, c * 4 + 2, base + 2);
            FPS_DIR(hx[c].w, hy[c].w, hz[c].w, c * 4 + 3, base + 3);
        }
#undef FPS_DIR

#define FPS_SH(VX, VY, VZ, SLOT, PO, IDX)                                      \
        do {                                                                   \
            float q = __fmaf_rn((VX), m2x, __fmaf_rn((VY), m2y,                \
                        __fmaf_rn((VZ), m2z, cc)));                            \
            float Dn = fminf(D[SLOT], q);                                      \
            D[SLOT] = Dn;                                                      \
            float dn = __fadd_rn(Dn, pn[PO]);                                  \
            if (dn > best) { best = dn; bidx = (IDX); }                        \
        } while (0)

#pragma unroll
        for (int ch = 2; ch < 8; ch++) {
            const int base = ch * CH_PTS + t * 4;
            const int o = (ch - 2) * 4;
            float4 px = *(const float4*)(sxp + base);
            float4 py = *(const float4*)(syp + base);
            float4 pz = *(const float4*)(szp + base);
            FPS_SH(px.x, py.x, pz.x, ch * 4 + 0, o + 0, base + 0);
            FPS_SH(px.y, py.y, pz.y, ch * 4 + 1, o + 1, base + 1);
            FPS_SH(px.z, py.z, pz.z, ch * 4 + 2, o + 2, base + 2);
            FPS_SH(px.w, py.w, pz.w, ch * 4 + 3, o + 3, base + 3);
        }
#undef FPS_SH

        unsigned gidx = (unsigned)((rank << 14) + bidx);

        unsigned bb = __float_as_uint(best);
        unsigned mv = __reduce_max_sync(0xffffffffu, bb);
        unsigned cand = (bb == mv) ? gidx : 0xffffffffu;
        unsigned mi = __reduce_min_sync(0xffffffffu, cand);
        if ((t & 31) == 0) { s_val[wrp] = mv; s_idx[wrp] = mi; }

        if (wrp != 0) {
            BAR_ARRIVE_1();
        } else {
            BAR_SYNC_1();
            unsigned wv = (t < 16) ? s_val[t] : 0u;
            unsigned wi = (t < 16) ? s_idx[t] : 0xffffffffu;
            unsigned mv2 = __reduce_max_sync(0xffffffffu, wv);
            unsigned cand2 = (wv == mv2) ? wi : 0xffffffffu;
            unsigned mi2 = __reduce_min_sync(0xffffffffu, cand2);
            if (t == 0) {
                int loc = (int)(mi2 & (HALF_N - 1));
                float wx = sxp[loc], wy = syp[loc], wz = szp[loc];
                mb[buf][rank][0] = __uint_as_float(mv2);
                mb[buf][rank][1] = __uint_as_float(mi2);
                mb[buf][rank][2] = wx;
                mb[buf][rank][3] = wy;
                mb[buf][rank][4] = wz;
                mbar_arrive_local(xbar_a);
                st_peer_entry(smem_u32(&mb[buf][rank][0]), peer,
                              mv2, mi2,
                              __float_as_uint(wx), __float_as_uint(wy),
                              __float_as_uint(wz));
                mbar_arrive_peer(xbar_a, peer);
            }
        }
        mbar_wait_parity(xbar_a, (unsigned)((k - 1) & 1));

        unsigned v0 = __float_as_uint(mb[buf][0][0]);
        unsigned v1 = __float_as_uint(mb[buf][1][0]);
        unsigned i0 = __float_as_uint(mb[buf][0][1]);
        unsigned i1 = __float_as_uint(mb[buf][1][1]);
        int w = (v1 > v0 || (v1 == v0 && i1 < i0)) ? 1 : 0;
        cx = mb[buf][w][2];
        cy = mb[buf][w][3];
        cz = mb[buf][w][4];

        if (rank == 0 && t == 0) {
            float* o = out_xyz + ((size_t)b * NQ + k) * 3;
            o[0] = cx; o[1] = cy; o[2] = cz;
        }
        buf ^= 1;
    }
}

// ---------------------------------------------------------------------------
// Fused fourier pos-embed + 2-layer MLP.
// Weight tiles: 32 c-rows, double-buffered, streamed via cp.async so the
// L2 round trip for tile tt+1 hides behind the 32-c compute of tile tt.
// ---------------------------------------------------------------------------
#define MT 512
#define PPITCH 132
#define WTP 260
#define WT_ROWS 32

__device__ __forceinline__ void gemm_layer(
    const float* __restrict__ Pm, float* __restrict__ WtA, float* __restrict__ WtB,
    const float* __restrict__ W, unsigned long long acc2[8][4],
    int t, int tn, int td)
{
    const uint32_t wa = smem_u32(WtA);
    const uint32_t wb = smem_u32(WtB);

    // prefetch tile 0 into buffer A
#pragma unroll
    for (int r = 0; r < 16; r++) {
        int i = r * MT + t;
        int c = i & 31, d = i >> 5;
        cp_async_f32(wa + (uint32_t)(c * WTP + d) * 4, W + (size_t)d * 256 + c);
    }
    CP_COMMIT();

    for (int tt = 0; tt < 8; tt++) {
        CP_WAIT0();
        __syncthreads();
        if (tt < 7) {
            const uint32_t dst = (tt & 1) ? wa : wb;   // tile tt+1's buffer
            const int col0 = (tt + 1) * WT_ROWS;
#pragma unroll
            for (int r = 0; r < 16; r++) {
                int i = r * MT + t;
                int c = i & 31, d = i >> 5;
                cp_async_f32(dst + (uint32_t)(c * WTP + d) * 4,
                             W + (size_t)d * 256 + col0 + c);
            }
            CP_COMMIT();
        }
        const float* Wt = (tt & 1) ? WtB : WtA;
#pragma unroll 4
        for (int c = 0; c < WT_ROWS; c++) {
            const float* pr = Pm + (tt * WT_ROWS + c) * PPITCH + 8 * tn;
            float4 p0 = *(const float4*)pr;
            float4 p1 = *(const float4*)(pr + 4);
            const float* wr = Wt + c * WTP + 8 * td;
            float4 w0 = *(const float4*)wr;
            float4 w1 = *(const float4*)(wr + 4);
            unsigned long long pv2[4] = {pack2(p0.x, p0.y), pack2(p0.z, p0.w),
                                         pack2(p1.x, p1.y), pack2(p1.z, p1.w)};
            float wv[8] = {w0.x, w0.y, w0.z, w0.w, w1.x, w1.y, w1.z, w1.w};
#pragma unroll
            for (int i = 0; i < 8; i++) {
                unsigned long long wv2 = pack2(wv[i], wv[i]);
#pragma unroll
                for (int j = 0; j < 4; j++)
                    ffma2(acc2[i][j], wv2, pv2[j]);
            }
        }
        __syncthreads();
    }
}

__global__ __launch_bounds__(MT, 1)
void mlp_kernel(const float* __restrict__ qxyz,
                const float* __restrict__ pc_min, const float* __restrict__ pc_max,
                const float* __restrict__ gB,
                const float* __restrict__ W1, const float* __restrict__ b1,
                const float* __restrict__ W2, const float* __restrict__ b2,
                float* __restrict__ out_emb) {
    extern __shared__ float sm[];
    float* Pm  = sm;                               // [256][PPITCH]
    float* WtA = sm + 256 * PPITCH;                // [32][WTP]
    float* WtB = WtA + WT_ROWS * WTP;              // [32][WTP]
    float* qn  = WtB + WT_ROWS * WTP;              // [3][128]

    const int b  = blockIdx.x >> 1;
    const int n0 = (blockIdx.x & 1) * 128;
    const int t  = threadIdx.x;
    const int tn = t & 15;
    const int td = t >> 4;

    if (t < 128) {
        const float* p = qxyz + ((size_t)b * NQ + n0 + t) * 3;
#pragma unroll
        for (int a = 0; a < 3; a++) {
            float mn = pc_min[b * 3 + a];
            float mx = pc_max[b * 3 + a];
            qn[a * 128 + t] = (p[a] - mn) / (mx - mn);
        }
    }
    __syncthreads();

    const float TWO_PI = 6.28318530717958647692f;
#pragma unroll
    for (int r = 0; r < 32; r++) {
        int i = r * MT + t;
        int n = i & 127;
        int f = i >> 7;
        float pr = qn[n] * gB[f] + qn[128 + n] * gB[128 + f] + qn[256 + n] * gB[256 + f];
        pr *= TWO_PI;
        float s, c;
        __sincosf(pr, &s, &c);
        Pm[f * PPITCH + n]          = s;
        Pm[(f + 128) * PPITCH + n]  = c;
    }
    __syncthreads();   // Pm complete before any tile-compute reads it

    unsigned long long acc2[8][4];

    // ===== layer 1: H = relu(W1 @ P + b1) =====
#pragma unroll
    for (int i = 0; i < 8; i++)
#pragma unroll
        for (int j = 0; j < 4; j++) acc2[i][j] = 0ull;

    gemm_layer(Pm, WtA, WtB, W1, acc2, t, tn, td);

#pragma unroll
    for (int i = 0; i < 8; i++) {
        int d = 8 * td + i;
        float bb = b1[d];
        float v[8];
#pragma unroll
        for (int j = 0; j < 4; j++) unpack2(v[2 * j], v[2 * j + 1], acc2[i][j]);
        float* hr = Pm + d * PPITCH + 8 * tn;
        float4 o0 = make_float4(fmaxf(v[0] + bb, 0.f), fmaxf(v[1] + bb, 0.f),
                                fmaxf(v[2] + bb, 0.f), fmaxf(v[3] + bb, 0.f));
        float4 o1 = make_float4(fmaxf(v[4] + bb, 0.f), fmaxf(v[5] + bb, 0.f),
                                fmaxf(v[6] + bb, 0.f), fmaxf(v[7] + bb, 0.f));
        *(float4*)hr       = o0;
        *(float4*)(hr + 4) = o1;
    }
    __syncthreads();   // H complete before layer-2 reads Pm

    // ===== layer 2: E = relu(W2 @ H + b2) =====
#pragma unroll
    for (int i = 0; i < 8; i++)
#pragma unroll
        for (int j = 0; j < 4; j++) acc2[i][j] = 0ull;

    gemm_layer(Pm, WtA, WtB, W2, acc2, t, tn, td);

#pragma unroll
    for (int i = 0; i < 8; i++) {
        int d = 8 * td + i;
        float bb = b2[d];
        float v[8];
#pragma unroll
        for (int j = 0; j < 4; j++) unpack2(v[2 * j], v[2 * j + 1], acc2[i][j]);
        float* dst = out_emb + ((size_t)b * DD + d) * NQ + n0 + 8 * tn;
        float4 o0 = make_float4(fmaxf(v[0] + bb, 0.f), fmaxf(v[1] + bb, 0.f),
                                fmaxf(v[2] + bb, 0.f), fmaxf(v[3] + bb, 0.f));
        float4 o1 = make_float4(fmaxf(v[4] + bb, 0.f), fmaxf(v[5] + bb, 0.f),
                                fmaxf(v[6] + bb, 0.f), fmaxf(v[7] + bb, 0.f));
        *(float4*)dst       = o0;
        *(float4*)(dst + 4) = o1;
    }
}

// ---------------------------------------------------------------------------
// launch
// ---------------------------------------------------------------------------
extern "C" void kernel_launch(void* const* d_in, const int* in_sizes, int n_in,
                              void* d_out, int out_size) {
    const float* xyz   = (const float*)d_in[0];
    const float* pcmin = (const float*)d_in[1];
    const float* pcmax = (const float*)d_in[2];
    const float* gB    = (const float*)d_in[3];
    const float* W1    = (const float*)d_in[4];
    const float* b1    = (const float*)d_in[5];
    const float* W2    = (const float*)d_in[6];
    const float* b2    = (const float*)d_in[7];

    float* out     = (float*)d_out;
    float* out_xyz = out;                              // [B][NQ][3]
    float* out_emb = out + (size_t)BB * NQ * 3;        // [B][D][NQ]

    const int fps_smem = 3 * HALF_N * 4;               // 196608 B
    const int mlp_smem = (256 * PPITCH + 2 * WT_ROWS * WTP + 3 * 128) * 4;
    cudaFuncSetAttribute(fps_kernel, cudaFuncAttributeMaxDynamicSharedMemorySize, fps_smem);
    cudaFuncSetAttribute(mlp_kernel, cudaFuncAttributeMaxDynamicSharedMemorySize, mlp_smem);

    fps_kernel<<<BB * 2, TPB, fps_smem>>>(xyz, out_xyz);
    mlp_kernel<<<BB * 2, MT, mlp_smem>>>(out_xyz, pcmin, pcmax, gB,
                                         W1, b1, W2, b2, out_emb);
}

// round 17
// speedup vs baseline: 1.3337x; 1.1590x over previous
#include <cuda_runtime.h>
#include <math.h>
#include <stdint.h>

#define BB 64
#define NN 32768
#define NQ 256
#define DD 256
#define HALF_N 16384   // points per CTA (cluster of 2)
#define TPB 512        // FPS threads per CTA (128-reg budget)
#define CH_PTS 2048    // points per chunk = TPB * 4

// ---------------------------------------------------------------------------
// helpers
// ---------------------------------------------------------------------------
__device__ __forceinline__ uint32_t smem_u32(const void* p) {
    uint32_t a;
    asm("{ .reg .u64 t; cvta.to.shared.u64 t, %1; cvt.u32.u64 %0, t; }"
        : "=r"(a) : "l"(p));
    return a;
}

#define CLUSTER_SYNC_()                                                  \
    do {                                                                 \
        asm volatile("barrier.cluster.arrive.aligned;" ::: "memory");    \
        asm volatile("barrier.cluster.wait.aligned;" ::: "memory");      \
    } while (0)

__device__ __forceinline__ void mbar_init(uint32_t a, uint32_t count) {
    asm volatile("mbarrier.init.shared.b64 [%0], %1;" :: "r"(a), "r"(count) : "memory");
}
// arrive on own barrier AND declare 24 expected tx bytes (release semantics)
__device__ __forceinline__ void mbar_expect_tx_arrive(uint32_t a, uint32_t bytes) {
    asm volatile("mbarrier.arrive.expect_tx.shared.b64 _, [%0], %1;"
                 :: "r"(a), "r"(bytes) : "memory");
}
__device__ __forceinline__ void mbar_wait_parity(uint32_t a, uint32_t parity) {
    asm volatile(
        "{\n\t"
        ".reg .pred P;\n\t"
        "WL_%=:\n\t"
        "mbarrier.try_wait.parity.acquire.cluster.shared::cta.b64 P, [%0], %1, 0x989680;\n\t"
        "@P bra.uni WD_%=;\n\t"
        "bra.uni WL_%=;\n\t"
        "WD_%=:\n\t"
        "}"
        :: "r"(a), "r"(parity) : "memory");
}

// fused store+signal: deliver 24 bytes into peer's mailbox slot, crediting the
// peer's mbarrier with complete_tx as the data lands (single cross-CTA transit)
__device__ __forceinline__ void st_async_peer3(uint32_t laddr, uint32_t lbar, uint32_t peer,
                                               unsigned long long v0,
                                               unsigned long long v1,
                                               unsigned long long v2) {
    asm volatile(
        "{\n\t"
        ".reg .b32 ra, rb;\n\t"
        "mapa.shared::cluster.u32 ra, %0, %2;\n\t"
        "mapa.shared::cluster.u32 rb, %1, %2;\n\t"
        "st.async.shared::cluster.mbarrier::complete_tx::bytes.b64 [ra], %3, [rb];\n\t"
        "st.async.shared::cluster.mbarrier::complete_tx::bytes.b64 [ra+8], %4, [rb];\n\t"
        "st.async.shared::cluster.mbarrier::complete_tx::bytes.b64 [ra+16], %5, [rb];\n\t"
        "}"
        :: "r"(laddr), "r"(lbar), "r"(peer), "l"(v0), "l"(v1), "l"(v2)
        : "memory");
}

#define BAR_ARRIVE_1()  asm volatile("bar.arrive 1, 512;" ::: "memory")
#define BAR_SYNC_1()    asm volatile("bar.sync 1, 512;" ::: "memory")

// packed f32x2 fma (MLP; benched equal to scalar)
__device__ __forceinline__ void ffma2(unsigned long long& acc,
                                      unsigned long long a, unsigned long long b) {
    asm("fma.rn.f32x2 %0, %1, %2, %0;" : "+l"(acc) : "l"(a), "l"(b));
}
__device__ __forceinline__ unsigned long long pack2u(unsigned lo, unsigned hi) {
    unsigned long long r;
    asm("mov.b64 %0, {%1, %2};" : "=l"(r) : "r"(lo), "r"(hi));
    return r;
}
__device__ __forceinline__ unsigned long long pack2(float lo, float hi) {
    unsigned long long r;
    asm("mov.b64 %0, {%1, %2};" : "=l"(r) : "f"(lo), "f"(hi));
    return r;
}
__device__ __forceinline__ void unpack2(float& lo, float& hi, unsigned long long v) {
    asm("mov.b64 {%0, %1}, %2;" : "=f"(lo), "=f"(hi) : "l"(v));
}

// cp.async 4-byte G->S copy
__device__ __forceinline__ void cp_async_f32(uint32_t dst, const float* src) {
    asm volatile("cp.async.ca.shared.global [%0], [%1], 4;"
                 :: "r"(dst), "l"(src) : "memory");
}
#define CP_COMMIT() asm volatile("cp.async.commit_group;" ::: "memory")
#define CP_WAIT0()  asm volatile("cp.async.wait_group 0;" ::: "memory")

// ---------------------------------------------------------------------------
// FPS: 64 clusters x 2 CTAs, 512 threads x 32 pts/thread. Exchange via
// st.async fused data+signal; local side expect_tx(24)+arrive (count=1).
// ---------------------------------------------------------------------------
__global__ __launch_bounds__(TPB, 1) __cluster_dims__(2, 1, 1)
void fps_kernel(const float* __restrict__ xyz, float* __restrict__ out_xyz) {
    extern __shared__ float sm[];
    float* sxp = sm;
    float* syp = sm + HALF_N;
    float* szp = sm + 2 * HALF_N;

    __shared__ unsigned s_val[16];
    __shared__ unsigned s_idx[16];
    __shared__ __align__(16) float mb[2][2][8];   // [buf][src_rank][val,idx,x,y,z,pad]
    __shared__ __align__(8) unsigned long long xbar;

    const int b    = blockIdx.x >> 1;
    const int rank = blockIdx.x & 1;
    const int t    = threadIdx.x;
    const int wrp  = t >> 5;
    const uint32_t xbar_a = smem_u32(&xbar);

    if (t == 0) mbar_init(xbar_a, 1);   // one arrive: t0's expect_tx arrive

    const float* gx = xyz + ((size_t)b * NN + (size_t)rank * HALF_N) * 3;
    for (int i = t; i < HALF_N; i += TPB) {
        const float* p = gx + 3 * i;
        sxp[i] = p[0];
        syp[i] = p[1];
        szp[i] = p[2];
    }

    const float* p0 = xyz + (size_t)b * NN * 3;
    float cx = __ldg(&p0[0]);
    float cy = __ldg(&p0[1]);
    float cz = __ldg(&p0[2]);
    if (rank == 0 && t == 0) {
        float* o = out_xyz + (size_t)b * NQ * 3;
        o[0] = cx; o[1] = cy; o[2] = cz;
    }
    __syncthreads();
    CLUSTER_SYNC_();   // peer's mbarrier init must be visible before st.async targets it

    // hoist chunks 0-1 coordinates into registers (loop-invariant)
    float4 hx[2], hy[2], hz[2];
#pragma unroll
    for (int c = 0; c < 2; c++) {
        const int base = c * CH_PTS + t * 4;
        hx[c] = *(const float4*)(sxp + base);
        hy[c] = *(const float4*)(syp + base);
        hz[c] = *(const float4*)(szp + base);
    }

    // |p|^2 for chunks 2-7 (one-time, 24 registers)
    float pn[24];
#pragma unroll
    for (int ch = 2; ch < 8; ch++) {
        const int base = ch * CH_PTS + t * 4;
        float4 px = *(const float4*)(sxp + base);
        float4 py = *(const float4*)(syp + base);
        float4 pz = *(const float4*)(szp + base);
        const int o = (ch - 2) * 4;
        pn[o + 0] = __fmaf_rn(px.x, px.x, __fmaf_rn(py.x, py.x, __fmul_rn(pz.x, pz.x)));
        pn[o + 1] = __fmaf_rn(px.y, px.y, __fmaf_rn(py.y, py.y, __fmul_rn(pz.y, pz.y)));
        pn[o + 2] = __fmaf_rn(px.z, px.z, __fmaf_rn(py.z, py.z, __fmul_rn(pz.z, pz.z)));
        pn[o + 3] = __fmaf_rn(px.w, px.w, __fmaf_rn(py.w, py.w, __fmul_rn(pz.w, pz.w)));
    }

    float D[32];
#pragma unroll
    for (int i = 0; i < 32; i++) D[i] = 1e10f;

    const uint32_t peer = 1 - rank;
    int buf = 1;

    for (int k = 1; k < NQ; k++) {
        const float m2x = -2.0f * cx;
        const float m2y = -2.0f * cy;
        const float m2z = -2.0f * cz;
        const float cc  = __fmaf_rn(cx, cx, __fmaf_rn(cy, cy, __fmul_rn(cz, cz)));

        float best = 0.0f;    // distances are >= 0
        int bidx = 0;

#define FPS_DIR(VX, VY, VZ, SLOT, IDX)                                         \
        do {                                                                   \
            float dx = (VX) - cx, dy = (VY) - cy, dz = (VZ) - cz;              \
            float dsq = __fmaf_rn(dx, dx, __fmaf_rn(dy, dy,                    \
                                  __fmul_rn(dz, dz)));                         \
            float dn = fminf(D[SLOT], dsq);                                    \
            D[SLOT] = dn;                                                      \
            if (dn > best) { best = dn; bidx = (IDX); }                        \
        } while (0)

#pragma unroll
        for (int c = 0; c < 2; c++) {
            const int base = c * CH_PTS + t * 4;
            FPS_DIR(hx[c].x, hy[c].x, hz[c].x, c * 4 + 0, base + 0);
            FPS_DIR(hx[c].y, hy[c].y, hz[c].y, c * 4 + 1, base + 1);
            FPS_DIR(hx[c].z, hy[c].z, hz[c].z, c * 4 + 2, base + 2);
            FPS_DIR(hx[c].w, hy[c].w, hz[c].w, c * 4 + 3, base + 3);
        }
#undef FPS_DIR

#define FPS_SH(VX, VY, VZ, SLOT, PO, IDX)                                      \
        do {                                                                   \
            float q = __fmaf_rn((VX), m2x, __fmaf_rn((VY), m2y,                \
                        __fmaf_rn((VZ), m2z, cc)));                            \
            float Dn = fminf(D[SLOT], q);                                      \
            D[SLOT] = Dn;                                                      \
            float dn = __fadd_rn(Dn, pn[PO]);                                  \
            if (dn > best) { best = dn; bidx = (IDX); }                        \
        } while (0)

#pragma unroll
        for (int ch = 2; ch < 8; ch++) {
            const int base = ch * CH_PTS + t * 4;
            const int o = (ch - 2) * 4;
            float4 px = *(const float4*)(sxp + base);
            float4 py = *(const float4*)(syp + base);
            float4 pz = *(const float4*)(szp + base);
            FPS_SH(px.x, py.x, pz.x, ch * 4 + 0, o + 0, base + 0);
            FPS_SH(px.y, py.y, pz.y, ch * 4 + 1, o + 1, base + 1);
            FPS_SH(px.z, py.z, pz.z, ch * 4 + 2, o + 2, base + 2);
            FPS_SH(px.w, py.w, pz.w, ch * 4 + 3, o + 3, base + 3);
        }
#undef FPS_SH

        unsigned gidx = (unsigned)((rank << 14) + bidx);

        unsigned bb = __float_as_uint(best);
        unsigned mv = __reduce_max_sync(0xffffffffu, bb);
        unsigned cand = (bb == mv) ? gidx : 0xffffffffu;
        unsigned mi = __reduce_min_sync(0xffffffffu, cand);
        if ((t & 31) == 0) { s_val[wrp] = mv; s_idx[wrp] = mi; }

        if (wrp != 0) {
            BAR_ARRIVE_1();
        } else {
            BAR_SYNC_1();
            unsigned wv = (t < 16) ? s_val[t] : 0u;
            unsigned wi = (t < 16) ? s_idx[t] : 0xffffffffu;
            unsigned mv2 = __reduce_max_sync(0xffffffffu, wv);
            unsigned cand2 = (wv == mv2) ? wi : 0xffffffffu;
            unsigned mi2 = __reduce_min_sync(0xffffffffu, cand2);
            if (t == 0) {
                int loc = (int)(mi2 & (HALF_N - 1));
                float wx = sxp[loc], wy = syp[loc], wz = szp[loc];
                // local mailbox
                mb[buf][rank][0] = __uint_as_float(mv2);
                mb[buf][rank][1] = __uint_as_float(mi2);
                mb[buf][rank][2] = wx;
                mb[buf][rank][3] = wy;
                mb[buf][rank][4] = wz;
                // own arrive + declare 24 bytes expected from peer (release)
                mbar_expect_tx_arrive(xbar_a, 24u);
                // fused store+signal into peer's mailbox slot [buf][rank]
                st_async_peer3(smem_u32(&mb[buf][rank][0]), xbar_a, peer,
                               pack2u(mv2, mi2),
                               pack2(wx, wy),
                               pack2(wz, 0.0f));
            }
        }
        mbar_wait_parity(xbar_a, (unsigned)((k - 1) & 1));

        unsigned v0 = __float_as_uint(mb[buf][0][0]);
        unsigned v1 = __float_as_uint(mb[buf][1][0]);
        unsigned i0 = __float_as_uint(mb[buf][0][1]);
        unsigned i1 = __float_as_uint(mb[buf][1][1]);
        int w = (v1 > v0 || (v1 == v0 && i1 < i0)) ? 1 : 0;
        cx = mb[buf][w][2];
        cy = mb[buf][w][3];
        cz = mb[buf][w][4];

        if (rank == 0 && t == 0) {
            float* o = out_xyz + ((size_t)b * NQ + k) * 3;
            o[0] = cx; o[1] = cy; o[2] = cz;
        }
        buf ^= 1;
    }
}

// ---------------------------------------------------------------------------
// Fused fourier pos-embed + 2-layer MLP (R16-proven, 123.5 us; unchanged).
// ---------------------------------------------------------------------------
#define MT 512
#define PPITCH 132
#define WTP 260
#define WT_ROWS 32

__device__ __forceinline__ void gemm_layer(
    const float* __restrict__ Pm, float* __restrict__ WtA, float* __restrict__ WtB,
    const float* __restrict__ W, unsigned long long acc2[8][4],
    int t, int tn, int td)
{
    const uint32_t wa = smem_u32(WtA);
    const uint32_t wb = smem_u32(WtB);

#pragma unroll
    for (int r = 0; r < 16; r++) {
        int i = r * MT + t;
        int c = i & 31, d = i >> 5;
        cp_async_f32(wa + (uint32_t)(c * WTP + d) * 4, W + (size_t)d * 256 + c);
    }
    CP_COMMIT();

    for (int tt = 0; tt < 8; tt++) {
        CP_WAIT0();
        __syncthreads();
        if (tt < 7) {
            const uint32_t dst = (tt & 1) ? wa : wb;
            const int col0 = (tt + 1) * WT_ROWS;
#pragma unroll
            for (int r = 0; r < 16; r++) {
                int i = r * MT + t;
                int c = i & 31, d = i >> 5;
                cp_async_f32(dst + (uint32_t)(c * WTP + d) * 4,
                             W + (size_t)d * 256 + col0 + c);
            }
            CP_COMMIT();
        }
        const float* Wt = (tt & 1) ? WtB : WtA;
#pragma unroll 4
        for (int c = 0; c < WT_ROWS; c++) {
            const float* pr = Pm + (tt * WT_ROWS + c) * PPITCH + 8 * tn;
            float4 p0 = *(const float4*)pr;
            float4 p1 = *(const float4*)(pr + 4);
            const float* wr = Wt + c * WTP + 8 * td;
            float4 w0 = *(const float4*)wr;
            float4 w1 = *(const float4*)(wr + 4);
            unsigned long long pv2[4] = {pack2(p0.x, p0.y), pack2(p0.z, p0.w),
                                         pack2(p1.x, p1.y), pack2(p1.z, p1.w)};
            float wv[8] = {w0.x, w0.y, w0.z, w0.w, w1.x, w1.y, w1.z, w1.w};
#pragma unroll
            for (int i = 0; i < 8; i++) {
                unsigned long long wv2 = pack2(wv[i], wv[i]);
#pragma unroll
                for (int j = 0; j < 4; j++)
                    ffma2(acc2[i][j], wv2, pv2[j]);
            }
        }
        __syncthreads();
    }
}

__global__ __launch_bounds__(MT, 1)
void mlp_kernel(const float* __restrict__ qxyz,
                const float* __restrict__ pc_min, const float* __restrict__ pc_max,
                const float* __restrict__ gB,
                const float* __restrict__ W1, const float* __restrict__ b1,
                const float* __restrict__ W2, const float* __restrict__ b2,
                float* __restrict__ out_emb) {
    extern __shared__ float sm[];
    float* Pm  = sm;                               // [256][PPITCH]
    float* WtA = sm + 256 * PPITCH;                // [32][WTP]
    float* WtB = WtA + WT_ROWS * WTP;              // [32][WTP]
    float* qn  = WtB + WT_ROWS * WTP;              // [3][128]

    const int b  = blockIdx.x >> 1;
    const int n0 = (blockIdx.x & 1) * 128;
    const int t  = threadIdx.x;
    const int tn = t & 15;
    const int td = t >> 4;

    if (t < 128) {
        const float* p = qxyz + ((size_t)b * NQ + n0 + t) * 3;
#pragma unroll
        for (int a = 0; a < 3; a++) {
            float mn = pc_min[b * 3 + a];
            float mx = pc_max[b * 3 + a];
            qn[a * 128 + t] = (p[a] - mn) / (mx - mn);
        }
    }
    __syncthreads();

    const float TWO_PI = 6.28318530717958647692f;
#pragma unroll
    for (int r = 0; r < 32; r++) {
        int i = r * MT + t;
        int n = i & 127;
        int f = i >> 7;
        float pr = qn[n] * gB[f] + qn[128 + n] * gB[128 + f] + qn[256 + n] * gB[256 + f];
        pr *= TWO_PI;
        float s, c;
        __sincosf(pr, &s, &c);
        Pm[f * PPITCH + n]          = s;
        Pm[(f + 128) * PPITCH + n]  = c;
    }
    __syncthreads();

    unsigned long long acc2[8][4];

#pragma unroll
    for (int i = 0; i < 8; i++)
#pragma unroll
        for (int j = 0; j < 4; j++) acc2[i][j] = 0ull;

    gemm_layer(Pm, WtA, WtB, W1, acc2, t, tn, td);

#pragma unroll
    for (int i = 0; i < 8; i++) {
        int d = 8 * td + i;
        float bb = b1[d];
        float v[8];
#pragma unroll
        for (int j = 0; j < 4; j++) unpack2(v[2 * j], v[2 * j + 1], acc2[i][j]);
        float* hr = Pm + d * PPITCH + 8 * tn;
        float4 o0 = make_float4(fmaxf(v[0] + bb, 0.f), fmaxf(v[1] + bb, 0.f),
                                fmaxf(v[2] + bb, 0.f), fmaxf(v[3] + bb, 0.f));
        float4 o1 = make_float4(fmaxf(v[4] + bb, 0.f), fmaxf(v[5] + bb, 0.f),
                                fmaxf(v[6] + bb, 0.f), fmaxf(v[7] + bb, 0.f));
        *(float4*)hr       = o0;
        *(float4*)(hr + 4) = o1;
    }
    __syncthreads();

#pragma unroll
    for (int i = 0; i < 8; i++)
#pragma unroll
        for (int j = 0; j < 4; j++) acc2[i][j] = 0ull;

    gemm_layer(Pm, WtA, WtB, W2, acc2, t, tn, td);

#pragma unroll
    for (int i = 0; i < 8; i++) {
        int d = 8 * td + i;
        float bb = b2[d];
        float v[8];
#pragma unroll
        for (int j = 0; j < 4; j++) unpack2(v[2 * j], v[2 * j + 1], acc2[i][j]);
        float* dst = out_emb + ((size_t)b * DD + d) * NQ + n0 + 8 * tn;
        float4 o0 = make_float4(fmaxf(v[0] + bb, 0.f), fmaxf(v[1] + bb, 0.f),
                                fmaxf(v[2] + bb, 0.f), fmaxf(v[3] + bb, 0.f));
        float4 o1 = make_float4(fmaxf(v[4] + bb, 0.f), fmaxf(v[5] + bb, 0.f),
                                fmaxf(v[6] + bb, 0.f), fmaxf(v[7] + bb, 0.f));
        *(float4*)dst       = o0;
        *(float4*)(dst + 4) = o1;
    }
}

// ---------------------------------------------------------------------------
// launch
// ---------------------------------------------------------------------------
extern "C" void kernel_launch(void* const* d_in, const int* in_sizes, int n_in,
                              void* d_out, int out_size) {
    const float* xyz   = (const float*)d_in[0];
    const float* pcmin = (const float*)d_in[1];
    const float* pcmax = (const float*)d_in[2];
    const float* gB    = (const float*)d_in[3];
    const float* W1    = (const float*)d_in[4];
    const float* b1    = (const float*)d_in[5];
    const float* W2    = (const float*)d_in[6];
    const float* b2    = (const float*)d_in[7];

    float* out     = (float*)d_out;
    float* out_xyz = out;                              // [B][NQ][3]
    float* out_emb = out + (size_t)BB * NQ * 3;        // [B][D][NQ]

    const int fps_smem = 3 * HALF_N * 4;               // 196608 B
    const int mlp_smem = (256 * PPITCH + 2 * WT_ROWS * WTP + 3 * 128) * 4;
    cudaFuncSetAttribute(fps_kernel, cudaFuncAttributeMaxDynamicSharedMemorySize, fps_smem);
    cudaFuncSetAttribute(mlp_kernel, cudaFuncAttributeMaxDynamicSharedMemorySize, mlp_smem);

    fps_kernel<<<BB * 2, TPB, fps_smem>>>(xyz, out_xyz);
    mlp_kernel<<<BB * 2, MT, mlp_smem>>>(out_xyz, pcmin, pcmax, gB,
                                         W1, b1, W2, b2, out_emb);
}